// round 1
// baseline (speedup 1.0000x reference)
#include <cuda_runtime.h>
#include <cuda_bf16.h>
#include <math_constants.h>

// Problem constants
#define BATCH   96
#define NW      10
#define NTOK    144            // window tokens
#define CDIM    192
#define HEADS   6
#define DH      32
#define MTOT    (BATCH*NW*NTOK)        // 138240
#define NHEADTOT (BATCH*NW*HEADS)      // 5760
#define NN2     (NTOK*NTOK)            // 20736
#define BIASTOT (NW*HEADS*NN2)         // 1244160
#define QKVN    (3*CDIM)               // 576
#define SCALE   0.17677669529663687f   // 32^-0.5

// -------- scratch (device globals; no runtime allocation allowed) ----------
__device__ float g_q[NHEADTOT * NTOK * DH];   // [head][n][d], pre-scaled
__device__ float g_k[NHEADTOT * NTOK * DH];
__device__ float g_v[NHEADTOT * NTOK * DH];
__device__ float g_att[MTOT * CDIM];          // attention output, [B,nW,N,C]
__device__ float g_bias[BIASTOT];             // [w][h][i*N+j]

// ---------------------------------------------------------------------------
// K0: materialize relative-position bias:  g_bias[(w*H+h)*NN2 + ij]
//       = bias_table[pidx[ij]*(NW*HEADS) + w*HEADS + h]
// ---------------------------------------------------------------------------
__global__ void build_bias_kernel(const float* __restrict__ bias_table,
                                  const int* __restrict__ pidx) {
    int idx = blockIdx.x * blockDim.x + threadIdx.x;
    if (idx >= BIASTOT) return;
    int wh = idx / NN2;
    int ij = idx - wh * NN2;
    g_bias[idx] = bias_table[pidx[ij] * (NW * HEADS) + wh];
}

// ---------------------------------------------------------------------------
// K1: QKV GEMM  X[M,192] @ W[192,576] + b  -> scatter to g_q/g_k/g_v
//     head-major layout [(bw*H+h)][n][d];  q is pre-multiplied by SCALE.
// Tiling: BM=128, BN=64, BK=16, 256 threads, 8x4 per thread.
// ---------------------------------------------------------------------------
#define GBM 128
#define GBN 64
#define GBK 16

__global__ __launch_bounds__(256)
void qkv_gemm_kernel(const float* __restrict__ X,
                     const float* __restrict__ W,
                     const float* __restrict__ bqkv) {
    __shared__ float As[GBK][GBM];
    __shared__ float Bs[GBK][GBN];

    const int m0 = blockIdx.x * GBM;
    const int n0 = blockIdx.y * GBN;
    const int tid = threadIdx.x;
    const int tx = tid & 15;       // 0..15 col group
    const int ty = tid >> 4;       // 0..15 row group

    float acc[8][4];
    #pragma unroll
    for (int r = 0; r < 8; ++r)
        #pragma unroll
        for (int c = 0; c < 4; ++c) acc[r][c] = 0.f;

    for (int k0 = 0; k0 < CDIM; k0 += GBK) {
        // ---- load A tile (128 rows x 16 k) : 512 float4, 2 per thread ----
        #pragma unroll
        for (int l = 0; l < 2; ++l) {
            int idx = tid + l * 256;
            int row = idx >> 2;
            int c4  = idx & 3;
            float4 a = *(const float4*)(X + (size_t)(m0 + row) * CDIM + k0 + c4 * 4);
            As[c4 * 4 + 0][row] = a.x;
            As[c4 * 4 + 1][row] = a.y;
            As[c4 * 4 + 2][row] = a.z;
            As[c4 * 4 + 3][row] = a.w;
        }
        // ---- load B tile (16 k x 64 n): 256 float4, 1 per thread ----
        {
            int krow = tid >> 4;
            int c4   = tid & 15;
            *(float4*)&Bs[krow][c4 * 4] =
                *(const float4*)(W + (size_t)(k0 + krow) * QKVN + n0 + c4 * 4);
        }
        __syncthreads();

        #pragma unroll
        for (int k = 0; k < GBK; ++k) {
            float4 a0 = *(const float4*)&As[k][ty * 8];
            float4 a1 = *(const float4*)&As[k][ty * 8 + 4];
            float4 bb = *(const float4*)&Bs[k][tx * 4];
            float ar[8] = {a0.x, a0.y, a0.z, a0.w, a1.x, a1.y, a1.z, a1.w};
            float bc[4] = {bb.x, bb.y, bb.z, bb.w};
            #pragma unroll
            for (int r = 0; r < 8; ++r)
                #pragma unroll
                for (int c = 0; c < 4; ++c)
                    acc[r][c] = fmaf(ar[r], bc[c], acc[r][c]);
        }
        __syncthreads();
    }

    // ---- epilogue: bias add + scatter to q/k/v (float4 per row) ----
    const int cg = n0 + tx * 4;            // column (multiple of 4, never crosses a head)
    const int t  = cg / CDIM;              // 0=q,1=k,2=v
    const int rem = cg - t * CDIM;
    const int h  = rem >> 5;
    const int d  = rem & 31;
    float* dstbase = (t == 0) ? g_q : (t == 1) ? g_k : g_v;
    const float sc = (t == 0) ? SCALE : 1.0f;
    float4 bq = *(const float4*)(bqkv + cg);

    #pragma unroll
    for (int r = 0; r < 8; ++r) {
        int m  = m0 + ty * 8 + r;
        int bw = m / NTOK;
        int n  = m - bw * NTOK;
        float4 val;
        val.x = (acc[r][0] + bq.x) * sc;
        val.y = (acc[r][1] + bq.y) * sc;
        val.z = (acc[r][2] + bq.z) * sc;
        val.w = (acc[r][3] + bq.w) * sc;
        *(float4*)&dstbase[(size_t)((bw * HEADS + h) * NTOK + n) * DH + d] = val;
    }
}

// ---------------------------------------------------------------------------
// K2: fused attention, one block per (b,w,h) head. 160 threads, 144 active
//     rows. K/V in smem (broadcast reads), bias+mask staged in smem tiles,
//     online softmax (registers ~q32 + o32 + st16).
// ---------------------------------------------------------------------------
__global__ __launch_bounds__(160)
void attn_kernel(const float* __restrict__ mask) {
    __shared__ float Ks[NTOK * DH];        // 18432 B
    __shared__ float Vs[NTOK * DH];        // 18432 B
    __shared__ float BMs[NTOK * 17];       // 9792 B  (pad 17: conflict-free column reads)

    const int head = blockIdx.x;           // = b*60 + w*6 + h
    const int h    = head % HEADS;
    const int bw   = head / HEADS;         // = b*NW + w
    const int b    = head / (NW * HEADS);
    const int t    = threadIdx.x;

    const float* kb = g_k + (size_t)head * NTOK * DH;
    const float* vb = g_v + (size_t)head * NTOK * DH;
    const float* qb = g_q + (size_t)head * NTOK * DH;
    const float* biasWH = g_bias + (size_t)(head % (NW * HEADS)) * NN2;  // (w*H+h)
    const float* maskB  = mask + (size_t)b * NN2;

    // cooperative K/V load (coalesced float4)
    for (int idx = t; idx < NTOK * DH / 4; idx += 160) {
        ((float4*)Ks)[idx] = ((const float4*)kb)[idx];
        ((float4*)Vs)[idx] = ((const float4*)vb)[idx];
    }

    // per-thread q row
    float q[DH];
    if (t < NTOK) {
        const float4* qr = (const float4*)(qb + t * DH);
        #pragma unroll
        for (int d4 = 0; d4 < 8; ++d4) {
            float4 v4 = qr[d4];
            q[d4 * 4 + 0] = v4.x; q[d4 * 4 + 1] = v4.y;
            q[d4 * 4 + 2] = v4.z; q[d4 * 4 + 3] = v4.w;
        }
    }

    float o[DH];
    #pragma unroll
    for (int d = 0; d < DH; ++d) o[d] = 0.f;
    float mrun = -CUDART_INF_F;
    float srun = 0.f;

    for (int jt = 0; jt < 9; ++jt) {       // 9 tiles of 16 keys
        __syncthreads();                   // also covers initial K/V load
        // stage bias+mask tile: rows 0..143, cols jt*16..+15
        for (int idx = t; idx < 576; idx += 160) {
            int row = idx >> 2;
            int c4  = idx & 3;
            int gi  = row * NTOK + jt * 16 + c4 * 4;
            float4 bb = *(const float4*)(biasWH + gi);
            float4 mm = *(const float4*)(maskB + gi);
            float* dst = &BMs[row * 17 + c4 * 4];
            dst[0] = bb.x + mm.x; dst[1] = bb.y + mm.y;
            dst[2] = bb.z + mm.z; dst[3] = bb.w + mm.w;
        }
        __syncthreads();

        if (t < NTOK) {
            float st[16];
            float tmax = -CUDART_INF_F;
            #pragma unroll
            for (int jj = 0; jj < 16; ++jj) {
                const int j = jt * 16 + jj;
                const float4* kr = (const float4*)(Ks + j * DH);
                float a0 = 0.f, a1 = 0.f, a2 = 0.f, a3 = 0.f;
                #pragma unroll
                for (int d4 = 0; d4 < 8; ++d4) {
                    float4 kv = kr[d4];                  // broadcast LDS
                    a0 = fmaf(q[d4 * 4 + 0], kv.x, a0);
                    a1 = fmaf(q[d4 * 4 + 1], kv.y, a1);
                    a2 = fmaf(q[d4 * 4 + 2], kv.z, a2);
                    a3 = fmaf(q[d4 * 4 + 3], kv.w, a3);
                }
                st[jj] = (a0 + a1) + (a2 + a3) + BMs[t * 17 + jj];
                tmax = fmaxf(tmax, st[jj]);
            }
            const float mnew = fmaxf(mrun, tmax);
            const float corr = __expf(mrun - mnew);      // 0 on first tile
            srun *= corr;
            #pragma unroll
            for (int d = 0; d < DH; ++d) o[d] *= corr;
            #pragma unroll
            for (int jj = 0; jj < 16; ++jj) {
                const float p = __expf(st[jj] - mnew);
                srun += p;
                const float4* vr = (const float4*)(Vs + (jt * 16 + jj) * DH);
                #pragma unroll
                for (int d4 = 0; d4 < 8; ++d4) {
                    float4 vv = vr[d4];                  // broadcast LDS
                    o[d4 * 4 + 0] = fmaf(p, vv.x, o[d4 * 4 + 0]);
                    o[d4 * 4 + 1] = fmaf(p, vv.y, o[d4 * 4 + 1]);
                    o[d4 * 4 + 2] = fmaf(p, vv.z, o[d4 * 4 + 2]);
                    o[d4 * 4 + 3] = fmaf(p, vv.w, o[d4 * 4 + 3]);
                }
            }
            mrun = mnew;
        }
    }

    if (t < NTOK) {
        const float inv = 1.0f / srun;
        float* op = g_att + ((size_t)bw * NTOK + t) * CDIM + h * DH;
        #pragma unroll
        for (int d4 = 0; d4 < 8; ++d4) {
            float4 v4;
            v4.x = o[d4 * 4 + 0] * inv; v4.y = o[d4 * 4 + 1] * inv;
            v4.z = o[d4 * 4 + 2] * inv; v4.w = o[d4 * 4 + 3] * inv;
            *(float4*)(op + d4 * 4) = v4;
        }
    }
}

// ---------------------------------------------------------------------------
// K3: projection GEMM  g_att[M,192] @ Wp[192,192] + bp  -> d_out
// Same tiling as K1, plain row-major epilogue.
// ---------------------------------------------------------------------------
__global__ __launch_bounds__(256)
void proj_gemm_kernel(const float* __restrict__ Wp,
                      const float* __restrict__ bp,
                      float* __restrict__ out) {
    __shared__ float As[GBK][GBM];
    __shared__ float Bs[GBK][GBN];

    const int m0 = blockIdx.x * GBM;
    const int n0 = blockIdx.y * GBN;
    const int tid = threadIdx.x;
    const int tx = tid & 15;
    const int ty = tid >> 4;

    float acc[8][4];
    #pragma unroll
    for (int r = 0; r < 8; ++r)
        #pragma unroll
        for (int c = 0; c < 4; ++c) acc[r][c] = 0.f;

    for (int k0 = 0; k0 < CDIM; k0 += GBK) {
        #pragma unroll
        for (int l = 0; l < 2; ++l) {
            int idx = tid + l * 256;
            int row = idx >> 2;
            int c4  = idx & 3;
            float4 a = *(const float4*)(g_att + (size_t)(m0 + row) * CDIM + k0 + c4 * 4);
            As[c4 * 4 + 0][row] = a.x;
            As[c4 * 4 + 1][row] = a.y;
            As[c4 * 4 + 2][row] = a.z;
            As[c4 * 4 + 3][row] = a.w;
        }
        {
            int krow = tid >> 4;
            int c4   = tid & 15;
            *(float4*)&Bs[krow][c4 * 4] =
                *(const float4*)(Wp + (size_t)(k0 + krow) * CDIM + n0 + c4 * 4);
        }
        __syncthreads();

        #pragma unroll
        for (int k = 0; k < GBK; ++k) {
            float4 a0 = *(const float4*)&As[k][ty * 8];
            float4 a1 = *(const float4*)&As[k][ty * 8 + 4];
            float4 bb = *(const float4*)&Bs[k][tx * 4];
            float ar[8] = {a0.x, a0.y, a0.z, a0.w, a1.x, a1.y, a1.z, a1.w};
            float bc[4] = {bb.x, bb.y, bb.z, bb.w};
            #pragma unroll
            for (int r = 0; r < 8; ++r)
                #pragma unroll
                for (int c = 0; c < 4; ++c)
                    acc[r][c] = fmaf(ar[r], bc[c], acc[r][c]);
        }
        __syncthreads();
    }

    const int cg = n0 + tx * 4;
    float4 bq = *(const float4*)(bp + cg);
    #pragma unroll
    for (int r = 0; r < 8; ++r) {
        int m = m0 + ty * 8 + r;
        float4 val;
        val.x = acc[r][0] + bq.x;
        val.y = acc[r][1] + bq.y;
        val.z = acc[r][2] + bq.z;
        val.w = acc[r][3] + bq.w;
        *(float4*)(out + (size_t)m * CDIM + cg) = val;
    }
}

// ---------------------------------------------------------------------------
extern "C" void kernel_launch(void* const* d_in, const int* in_sizes, int n_in,
                              void* d_out, int out_size) {
    const float* x          = (const float*)d_in[0];
    const float* mask       = (const float*)d_in[1];
    const float* w_qkv      = (const float*)d_in[2];
    const float* b_qkv      = (const float*)d_in[3];
    const float* w_proj     = (const float*)d_in[4];
    const float* b_proj     = (const float*)d_in[5];
    const float* bias_table = (const float*)d_in[6];
    const int*   pidx       = (const int*)d_in[7];
    float* out = (float*)d_out;

    build_bias_kernel<<<(BIASTOT + 255) / 256, 256>>>(bias_table, pidx);
    qkv_gemm_kernel<<<dim3(MTOT / GBM, QKVN / GBN), 256>>>(x, w_qkv, b_qkv);
    attn_kernel<<<NHEADTOT, 160>>>(mask);
    proj_gemm_kernel<<<dim3(MTOT / GBM, CDIM / GBN), 256>>>(w_proj, b_proj, out);
}